// round 4
// baseline (speedup 1.0000x reference)
#include <cuda_runtime.h>

// Problem constants: B=16, K=64, H=96, W=96
#define MAP_ELEMS   9216        // 96*96
#define MAP_QUADS   2304        // 9216/4
#define QUADS_PER_ROW 24        // 96/4
#define NMAPS       1024        // B*K
#define D_ELEMS     9437184     // 1024*9216
#define KP_BASE     18874368    // 2*D_ELEMS
#define KP_STACK    6144        // 16*192*2
#define Z_BASE      18886656    // KP_BASE + 2*KP_STACK
#define KP_PER_B    384         // 3*K*2

__device__ __forceinline__ float fast_sigmoid(float x) {
    return __fdividef(1.0f, 1.0f + __expf(-x));
}

__device__ __forceinline__ float precise_sigmoid(float x) {
    return 1.0f / (1.0f + expf(-x));   // IEEE div + accurate expf for decode path
}

__global__ __launch_bounds__(256)
void fused_sigmoid_decode_kernel(const float* __restrict__ Rk,
                                 const float* __restrict__ tfRk,
                                 float* __restrict__ out)
{
    const int bid = blockIdx.x;           // 0..2047
    const int s   = bid >> 10;            // stack: 0 = Rk, 1 = tf_Rk
    const int m   = bid & 1023;           // map index (b*64 + k)
    const int tid = threadIdx.x;

    const float* src = (s ? tfRk : Rk) + (size_t)m * MAP_ELEMS;
    float* dstD = out + (size_t)s * D_ELEMS + (size_t)m * MAP_ELEMS;

    const float4* in4  = (const float4*)src;
    float4*       out4 = (float4*)dstD;

    // --- fused sigmoid + weighted reductions (double accumulators) ---
    double dz = 0.0, dsx = 0.0, dsy = 0.0;

#pragma unroll
    for (int it = 0; it < MAP_QUADS / 256; ++it) {
        const int i = tid + it * 256;     // quad index 0..2303
        float4 v = __ldcs(&in4[i]);
        float4 g;
        g.x = fast_sigmoid(v.x);
        g.y = fast_sigmoid(v.y);
        g.z = fast_sigmoid(v.z);
        g.w = fast_sigmoid(v.w);
        __stcs(&out4[i], g);

        const int h  = i / QUADS_PER_ROW;             // row
        const int w0 = (i - h * QUADS_PER_ROW) * 4;   // first column of quad

        const float rs = (g.x + g.y) + (g.z + g.w);
        const float qx = rs * (float)w0 + (g.y + 2.0f * g.z + 3.0f * g.w);

        dz  += (double)rs;
        dsy += (double)rs * (double)h;
        dsx += (double)qx;
    }

    // --- warp reduce ---
#pragma unroll
    for (int off = 16; off > 0; off >>= 1) {
        dz  += __shfl_down_sync(0xffffffffu, dz,  off);
        dsx += __shfl_down_sync(0xffffffffu, dsx, off);
        dsy += __shfl_down_sync(0xffffffffu, dsy, off);
    }

    __shared__ double sh[8][3];
    const int warp = tid >> 5;
    const int lane = tid & 31;
    if (lane == 0) { sh[warp][0] = dz; sh[warp][1] = dsx; sh[warp][2] = dsy; }
    __syncthreads();

    if (tid == 0) {
        double z = 0.0, sx = 0.0, sy = 0.0;
#pragma unroll
        for (int w = 0; w < 8; ++w) { z += sh[w][0]; sx += sh[w][1]; sy += sh[w][2]; }

        const float zeta = (float)z;
        const float kpx  = rintf((float)(sx / z));    // jnp.round == half-to-even == rintf
        const float kpy  = rintf((float)(sy / z));

        int xi = (int)kpx; xi = xi < 0 ? 0 : (xi > 95 ? 95 : xi);
        int yi = (int)kpy; yi = yi < 0 ? 0 : (yi > 95 ? 95 : yi);

        // gather D[b,k,yi,xi]: recompute from input with precise sigmoid
        const float d = precise_sigmoid(src[yi * 96 + xi]);

        // match reference rounding: kp*d then add/sub, NO fma contraction
        const float tx = __fmul_rn(kpx, d);
        const float ty = __fmul_rn(kpy, d);
        const float k1x = truncf(__fadd_rn(kpx,  tx));
        const float k1y = truncf(__fadd_rn(kpy,  ty));
        const float k2x = truncf(__fadd_rn(kpx, -tx));
        const float k2y = truncf(__fadd_rn(kpy, -ty));

        const int b = m >> 6;
        const int k = m & 63;
        float* kp = out + KP_BASE + (size_t)s * KP_STACK + (size_t)b * KP_PER_B + k * 2;
        kp[0]   = kpx;  kp[1]   = kpy;    // keypoint[:, k,      :]
        kp[128] = k1x;  kp[129] = k1y;    // keypoint[:, K + k,  :]
        kp[256] = k2x;  kp[257] = k2y;    // keypoint[:, 2K + k, :]

        out[Z_BASE + (size_t)s * NMAPS + m] = zeta;
    }
}

extern "C" void kernel_launch(void* const* d_in, const int* in_sizes, int n_in,
                              void* d_out, int out_size) {
    const float* Rk   = (const float*)d_in[0];
    const float* tfRk = (const float*)d_in[1];
    float* out = (float*)d_out;
    (void)in_sizes; (void)n_in; (void)out_size;

    fused_sigmoid_decode_kernel<<<2048, 256>>>(Rk, tfRk, out);
}

// round 9
// speedup vs baseline: 2.1515x; 2.1515x over previous
#include <cuda_runtime.h>

// Problem constants: B=16, K=64, H=96, W=96
#define MAP_ELEMS   9216        // 96*96
#define MAP_QUADS   2304        // 9216/4
#define NMAPS       1024        // B*K
#define D_ELEMS     9437184     // 1024*9216
#define KP_BASE     18874368    // 2*D_ELEMS
#define KP_STACK    6144        // 16*192*2
#define Z_BASE      18886656    // KP_BASE + 2*KP_STACK
#define KP_PER_B    384         // 3*K*2

__device__ __forceinline__ float fast_sigmoid(float x) {
    return __fdividef(1.0f, 1.0f + __expf(-x));
}

// Kahan: running sum s, compensation c; corrected value = s - c
__device__ __forceinline__ void kahan_add(float& s, float& c, float v) {
    float y = __fadd_rn(v, -c);
    float t = __fadd_rn(s, y);
    c = __fadd_rn(__fadd_rn(t, -s), -y);
    s = t;
}

// TwoSum merge of two compensated pairs via shuffle (xor butterfly).
// Invariant preserved: exact = s - c.
__device__ __forceinline__ void shfl_merge(float& s, float& c, int off) {
    float s2 = __shfl_xor_sync(0xffffffffu, s, off);
    float c2 = __shfl_xor_sync(0xffffffffu, c, off);
    float t  = __fadd_rn(s, s2);
    float z  = __fadd_rn(t, -s);
    float e  = __fadd_rn(__fadd_rn(s, -__fadd_rn(t, -z)), __fadd_rn(s2, -z));
    s = t;
    c = __fadd_rn(__fadd_rn(c, c2), -e);
}

__global__ __launch_bounds__(256)
void fused_sigmoid_decode_kernel(const float* __restrict__ Rk,
                                 const float* __restrict__ tfRk,
                                 float* __restrict__ out)
{
    const int bid = blockIdx.x;           // 0..2047
    const int s   = bid >> 10;            // stack: 0 = Rk, 1 = tf_Rk
    const int m   = bid & 1023;           // map index (b*64 + k)
    const int tid = threadIdx.x;

    const float* src = (s ? tfRk : Rk) + (size_t)m * MAP_ELEMS;
    float* dstD = out + (size_t)s * D_ELEMS + (size_t)m * MAP_ELEMS;

    const float4* in4  = (const float4*)src;
    float4*       out4 = (float4*)dstD;

    // ---- Phase A: batch all 9 quad-loads (MLP = 9) ----
    float4 v[9];
#pragma unroll
    for (int it = 0; it < 9; ++it)
        v[it] = __ldcs(&in4[tid + it * 256]);

    // ---- Phase B: sigmoid + store + compensated fp32 reductions ----
    float sz = 0.f, cz = 0.f;   // zeta
    float sx = 0.f, cx = 0.f;   // sum s * x
    float sy = 0.f, cy = 0.f;   // sum s * y

    // quad index i = tid + 256*it; row h = i/24, quad-col qc = i%24.
    // 256 = 10*24 + 16 -> incremental update, no divisions in the loop.
    int h  = tid / 24;
    int qc = tid - h * 24;

#pragma unroll
    for (int it = 0; it < 9; ++it) {
        float4 g;
        g.x = fast_sigmoid(v[it].x);
        g.y = fast_sigmoid(v[it].y);
        g.z = fast_sigmoid(v[it].z);
        g.w = fast_sigmoid(v[it].w);
        __stcs(&out4[tid + it * 256], g);

        const float rs = (g.x + g.y) + (g.z + g.w);
        const float w0 = (float)(qc << 2);
        const float qx = fmaf(rs, w0, fmaf(3.0f, g.w, fmaf(2.0f, g.z, g.y)));
        const float qy = rs * (float)h;

        kahan_add(sz, cz, rs);
        kahan_add(sx, cx, qx);
        kahan_add(sy, cy, qy);

        qc += 16; h += 10;
        if (qc >= 24) { qc -= 24; ++h; }
    }

    // ---- warp reduce (compensated) ----
#pragma unroll
    for (int off = 16; off > 0; off >>= 1) {
        shfl_merge(sz, cz, off);
        shfl_merge(sx, cx, off);
        shfl_merge(sy, cy, off);
    }

    __shared__ float sh[8][6];
    const int warp = tid >> 5;
    const int lane = tid & 31;
    if (lane == 0) {
        sh[warp][0] = sz; sh[warp][1] = cz;
        sh[warp][2] = sx; sh[warp][3] = cx;
        sh[warp][4] = sy; sh[warp][5] = cy;
    }
    __syncthreads();

    if (tid == 0) {
        // tiny final merge in double (one thread, ~50 FP64 ops/block: negligible)
        double z = 0.0, tx = 0.0, ty = 0.0;
#pragma unroll
        for (int w = 0; w < 8; ++w) {
            z  += (double)sh[w][0] - (double)sh[w][1];
            tx += (double)sh[w][2] - (double)sh[w][3];
            ty += (double)sh[w][4] - (double)sh[w][5];
        }
        const float zeta = (float)z;
        const float fsx  = (float)tx;
        const float fsy  = (float)ty;

        // jnp.round == half-to-even == rintf; IEEE fp32 divide like the reference
        const float kpx = rintf(__fdiv_rn(fsx, zeta));
        const float kpy = rintf(__fdiv_rn(fsy, zeta));

        int xi = (int)kpx; xi = xi < 0 ? 0 : (xi > 95 ? 95 : xi);
        int yi = (int)kpy; yi = yi < 0 ? 0 : (yi > 95 ? 95 : yi);

        // gather D[b,k,yi,xi] from the sigmoid map this block just wrote (L2 hit)
        const float d = dstD[yi * 96 + xi];

        // match reference rounding: kp*d then add/sub, NO fma contraction
        const float mx = __fmul_rn(kpx, d);
        const float my = __fmul_rn(kpy, d);
        const float k1x = truncf(__fadd_rn(kpx,  mx));
        const float k1y = truncf(__fadd_rn(kpy,  my));
        const float k2x = truncf(__fadd_rn(kpx, -mx));
        const float k2y = truncf(__fadd_rn(kpy, -my));

        const int b = m >> 6;
        const int k = m & 63;
        float* kp = out + KP_BASE + (size_t)s * KP_STACK + (size_t)b * KP_PER_B + k * 2;
        kp[0]   = kpx;  kp[1]   = kpy;    // keypoint[:, k,      :]
        kp[128] = k1x;  kp[129] = k1y;    // keypoint[:, K + k,  :]
        kp[256] = k2x;  kp[257] = k2y;    // keypoint[:, 2K + k, :]

        out[Z_BASE + (size_t)s * NMAPS + m] = zeta;
    }
}

extern "C" void kernel_launch(void* const* d_in, const int* in_sizes, int n_in,
                              void* d_out, int out_size) {
    const float* Rk   = (const float*)d_in[0];
    const float* tfRk = (const float*)d_in[1];
    float* out = (float*)d_out;
    (void)in_sizes; (void)n_in; (void)out_size;

    fused_sigmoid_decode_kernel<<<2048, 256>>>(Rk, tfRk, out);
}

// round 10
// speedup vs baseline: 2.8805x; 1.3388x over previous
#include <cuda_runtime.h>

// Problem constants: B=16, K=64, H=96, W=96
#define MAP_ELEMS   9216        // 96*96
#define MAP_QUADS   2304        // 9216/4  = 768 * 3
#define NMAPS       1024        // B*K
#define D_ELEMS     9437184     // 1024*9216
#define KP_BASE     18874368    // 2*D_ELEMS
#define KP_STACK    6144        // 16*192*2
#define Z_BASE      18886656    // KP_BASE + 2*KP_STACK
#define KP_PER_B    384         // 3*K*2

#define NTHREADS    768
#define NWARPS      24
#define QPT         3           // quads per thread

__device__ __forceinline__ float fast_sigmoid(float x) {
    return __fdividef(1.0f, 1.0f + __expf(-x));
}

// Kahan: running sum s, compensation c; corrected value = s - c
__device__ __forceinline__ void kahan_add(float& s, float& c, float v) {
    float y = __fadd_rn(v, -c);
    float t = __fadd_rn(s, y);
    c = __fadd_rn(__fadd_rn(t, -s), -y);
    s = t;
}

// TwoSum merge of two compensated pairs via shuffle (xor butterfly).
// Invariant preserved: exact = s - c.  Zero pairs merge harmlessly.
__device__ __forceinline__ void shfl_merge(float& s, float& c, int off) {
    float s2 = __shfl_xor_sync(0xffffffffu, s, off);
    float c2 = __shfl_xor_sync(0xffffffffu, c, off);
    float t  = __fadd_rn(s, s2);
    float z  = __fadd_rn(t, -s);
    float e  = __fadd_rn(__fadd_rn(s, -__fadd_rn(t, -z)), __fadd_rn(s2, -z));
    s = t;
    c = __fadd_rn(__fadd_rn(c, c2), -e);
}

__global__ __launch_bounds__(NTHREADS, 2)
void fused_sigmoid_decode_kernel(const float* __restrict__ Rk,
                                 const float* __restrict__ tfRk,
                                 float* __restrict__ out)
{
    const int bid = blockIdx.x;           // 0..2047
    const int s   = bid >> 10;            // stack: 0 = Rk, 1 = tf_Rk
    const int m   = bid & 1023;           // map index (b*64 + k)
    const int tid = threadIdx.x;

    const float* src = (s ? tfRk : Rk) + (size_t)m * MAP_ELEMS;
    float* dstD = out + (size_t)s * D_ELEMS + (size_t)m * MAP_ELEMS;

    const float4* in4  = (const float4*)src;
    float4*       out4 = (float4*)dstD;

    // ---- Phase A: batch the 3 quad-loads ----
    float4 v[QPT];
#pragma unroll
    for (int it = 0; it < QPT; ++it)
        v[it] = __ldcs(&in4[tid + it * NTHREADS]);

    // ---- Phase B: sigmoid + store + compensated fp32 reductions ----
    float sz = 0.f, cz = 0.f;   // zeta
    float sx = 0.f, cx = 0.f;   // sum s * x
    float sy = 0.f, cy = 0.f;   // sum s * y

#pragma unroll
    for (int it = 0; it < QPT; ++it) {
        const int i  = tid + it * NTHREADS;   // quad index 0..2303
        const int h  = i / 24;                // row
        const int qc = i - h * 24;            // quad-column

        float4 g;
        g.x = fast_sigmoid(v[it].x);
        g.y = fast_sigmoid(v[it].y);
        g.z = fast_sigmoid(v[it].z);
        g.w = fast_sigmoid(v[it].w);
        out4[i] = g;                          // plain store: keep in L2

        const float rs = (g.x + g.y) + (g.z + g.w);
        const float w0 = (float)(qc << 2);
        const float qx = fmaf(rs, w0, fmaf(3.0f, g.w, fmaf(2.0f, g.z, g.y)));
        const float qy = rs * (float)h;

        kahan_add(sz, cz, rs);
        kahan_add(sx, cx, qx);
        kahan_add(sy, cy, qy);
    }

    // ---- warp reduce (compensated butterfly) ----
#pragma unroll
    for (int off = 16; off > 0; off >>= 1) {
        shfl_merge(sz, cz, off);
        shfl_merge(sx, cx, off);
        shfl_merge(sy, cy, off);
    }

    __shared__ float sh[NWARPS][6];
    const int warp = tid >> 5;
    const int lane = tid & 31;
    if (lane == 0) {
        sh[warp][0] = sz; sh[warp][1] = cz;
        sh[warp][2] = sx; sh[warp][3] = cx;
        sh[warp][4] = sy; sh[warp][5] = cy;
    }
    __syncthreads();

    // ---- warp 0: merge 24 partials via TwoSum butterfly, then decode ----
    if (tid < 32) {
        float az = 0.f, bz = 0.f, ax = 0.f, bx = 0.f, ay = 0.f, by = 0.f;
        if (tid < NWARPS) {
            az = sh[tid][0]; bz = sh[tid][1];
            ax = sh[tid][2]; bx = sh[tid][3];
            ay = sh[tid][4]; by = sh[tid][5];
        }
#pragma unroll
        for (int off = 16; off > 0; off >>= 1) {
            shfl_merge(az, bz, off);
            shfl_merge(ax, bx, off);
            shfl_merge(ay, by, off);
        }

        if (tid == 0) {
            // exact correction in double (3 DADDs only)
            const double zd = (double)az - (double)bz;
            const double xd = (double)ax - (double)bx;
            const double yd = (double)ay - (double)by;

            const float zeta = (float)zd;
            const float fsx  = (float)xd;
            const float fsy  = (float)yd;

            // jnp.round == half-to-even == rintf; IEEE fp32 divide like reference
            const float kpx = rintf(__fdiv_rn(fsx, zeta));
            const float kpy = rintf(__fdiv_rn(fsy, zeta));

            int xi = (int)kpx; xi = xi < 0 ? 0 : (xi > 95 ? 95 : xi);
            int yi = (int)kpy; yi = yi < 0 ? 0 : (yi > 95 ? 95 : yi);

            // gather D[b,k,yi,xi] from the sigmoid map this block just wrote (L2 hit)
            const float d = dstD[yi * 96 + xi];

            // match reference rounding: kp*d then add/sub, NO fma contraction
            const float mx = __fmul_rn(kpx, d);
            const float my = __fmul_rn(kpy, d);
            const float k1x = truncf(__fadd_rn(kpx,  mx));
            const float k1y = truncf(__fadd_rn(kpy,  my));
            const float k2x = truncf(__fadd_rn(kpx, -mx));
            const float k2y = truncf(__fadd_rn(kpy, -my));

            const int b = m >> 6;
            const int k = m & 63;
            float* kp = out + KP_BASE + (size_t)s * KP_STACK + (size_t)b * KP_PER_B + k * 2;
            kp[0]   = kpx;  kp[1]   = kpy;    // keypoint[:, k,      :]
            kp[128] = k1x;  kp[129] = k1y;    // keypoint[:, K + k,  :]
            kp[256] = k2x;  kp[257] = k2y;    // keypoint[:, 2K + k, :]

            out[Z_BASE + (size_t)s * NMAPS + m] = zeta;
        }
    }
}

extern "C" void kernel_launch(void* const* d_in, const int* in_sizes, int n_in,
                              void* d_out, int out_size) {
    const float* Rk   = (const float*)d_in[0];
    const float* tfRk = (const float*)d_in[1];
    float* out = (float*)d_out;
    (void)in_sizes; (void)n_in; (void)out_size;

    fused_sigmoid_decode_kernel<<<2048, NTHREADS>>>(Rk, tfRk, out);
}